// round 5
// baseline (speedup 1.0000x reference)
#include <cuda_runtime.h>
#include <cstdint>

#define KBINS 8
#define BVAL 3.0f
#define DIMN 32
#define HID 32
#define LNUM 31
#define NP 23
#define MIN_BW 1e-3f
#define MIN_D 1e-3f
#define BATCH 65536
#define CPAD 0.5397416f  // log(exp(1-MIN_D)-1)

typedef unsigned long long u64;

__device__ __forceinline__ u64 pack2(float a, float b) {
    u64 r;
    uint32_t lo = __float_as_uint(a), hi = __float_as_uint(b);
    asm("mov.b64 %0, {%1, %2};" : "=l"(r) : "r"(lo), "r"(hi));
    return r;
}
__device__ __forceinline__ void unpack2(u64 v, float& a, float& b) {
    uint32_t lo, hi;
    asm("mov.b64 {%0, %1}, %2;" : "=r"(lo), "=r"(hi) : "l"(v));
    a = __uint_as_float(lo); b = __uint_as_float(hi);
}
__device__ __forceinline__ u64 ffma2(u64 a, u64 b, u64 c) {
    u64 d;
    asm("fma.rn.f32x2 %0, %1, %2, %3;" : "=l"(d) : "l"(a), "l"(b), "l"(c));
    return d;
}

__device__ __forceinline__ float fast_tanh(float x) {
    float e = __expf(2.0f * x);
    return 1.0f - __fdividef(2.0f, e + 1.0f);
}
__device__ __forceinline__ float softplusf(float x) {
    return fmaxf(x, 0.0f) + __logf(1.0f + __expf(-fabsf(x)));
}

__device__ __forceinline__ void softmax8(const float* p, float scale, float* out) {
    float m = p[0];
#pragma unroll
    for (int i = 1; i < KBINS; i++) m = fmaxf(m, p[i]);
    float s = 0.0f;
#pragma unroll
    for (int i = 0; i < KBINS; i++) { out[i] = __expf(p[i] - m); s += out[i]; }
    float inv = __fdividef(scale, s);
#pragma unroll
    for (int i = 0; i < KBINS; i++) out[i] *= inv;
}
// inputs in (0, 2B] -> no max subtraction needed
__device__ __forceinline__ void softmax8_nm(const float* p, float scale, float* out) {
    float s = 0.0f;
#pragma unroll
    for (int i = 0; i < KBINS; i++) { out[i] = __expf(p[i]); s += out[i]; }
    float inv = __fdividef(scale, s);
#pragma unroll
    for (int i = 0; i < KBINS; i++) out[i] *= inv;
}

__device__ __forceinline__ float spline_fwd(float xin, const float* p, float* ldo) {
    float cw[KBINS + 1], ch[KBINS + 1];
    {
        float wu[KBINS], w_[KBINS];
        softmax8(p, 2.0f * BVAL, wu);
        softmax8_nm(wu, 1.0f - MIN_BW * KBINS, w_);
        cw[0] = -BVAL;
        float c = 0.0f;
#pragma unroll
        for (int k = 0; k < KBINS; k++) { c += w_[k] + MIN_BW; cw[k + 1] = 2.0f * BVAL * c - BVAL; }
        cw[KBINS] = BVAL;
    }
    {
        float hu[KBINS], h_[KBINS];
        softmax8(p + KBINS, 2.0f * BVAL, hu);
        softmax8_nm(hu, 1.0f - MIN_BW * KBINS, h_);
        ch[0] = -BVAL;
        float c = 0.0f;
#pragma unroll
        for (int k = 0; k < KBINS; k++) { c += h_[k] + MIN_BW; ch[k + 1] = 2.0f * BVAL * c - BVAL; }
        ch[KBINS] = BVAL;
    }

    float dv[KBINS + 1];
    {
        float de = MIN_D + softplusf(CPAD);
        dv[0] = de; dv[KBINS] = de;
#pragma unroll
        for (int j = 0; j < KBINS - 1; j++)
            dv[j + 1] = MIN_D + softplusf(softplusf(p[2 * KBINS + j]));
    }

    bool inside = (xin >= -BVAL) && (xin <= BVAL);
    float xc = fminf(fmaxf(xin, -BVAL), BVAL);

    float in_cw = cw[0], in_ch = ch[0];
    float in_w = cw[1] - cw[0], in_h = ch[1] - ch[0];
    float d0 = dv[0], d1 = dv[1];
#pragma unroll
    for (int k = 1; k < KBINS; k++) {
        if (xc >= cw[k]) {
            in_cw = cw[k]; in_ch = ch[k];
            in_w = cw[k + 1] - cw[k]; in_h = ch[k + 1] - ch[k];
            d0 = dv[k]; d1 = dv[k + 1];
        }
    }

    float invw = __fdividef(1.0f, in_w);
    float delta = in_h * invw;
    float th = (xc - in_cw) * invw;
    float tt = th * (1.0f - th);
    float num = in_h * (delta * th * th + d0 * tt);
    float den = delta + (d0 + d1 - 2.0f * delta) * tt;
    float outv = in_ch + __fdividef(num, den);
    float omt = 1.0f - th;
    float dnum = delta * delta * (d1 * th * th + 2.0f * delta * tt + d0 * omt * omt);
    float ld = __logf(dnum) - 2.0f * __logf(den);

    *ldo = inside ? ld : 0.0f;
    return inside ? outv : xin;
}

// 128 threads/block; each thread owns elements (b0+t, b0+128+t) packed into
// f32x2 register pairs. Weights duplicated {w,w} in smem -> 1 LDS.64 + 1 FFMA2
// per weight for 2 batch elements.
__global__ __launch_bounds__(128, 2) void nsf_ar_kernel(
    const float* __restrict__ x, const float* __restrict__ init_param,
    const float* __restrict__ w1, const float* __restrict__ b1,
    const float* __restrict__ w2, const float* __restrict__ b2,
    const float* __restrict__ w3, const float* __restrict__ b3,
    float* __restrict__ zout, float* __restrict__ ldout, int write_ld)
{
    __shared__ u64 xp[128 * 33];     // packed x: {x[t][d], x[t+128][d]}
    __shared__ u64 w1p[31 * 32];
    __shared__ u64 w2p[32 * 32];
    __shared__ u64 w3p[32 * 24];     // row stride 24 (col 23 unused)
    __shared__ u64 b1p[32], b2p[32], b3p[NP];

    const int t = threadIdx.x;
    const int b0 = blockIdx.x * 256;

    // stage x: coalesced float4 LDG, scatter into packed halves
    {
        float* xpf = (float*)xp;
        const float4* gx = (const float4*)(x + (size_t)b0 * 32);
        for (int i = t; i < 256 * 8; i += 128) {
            float4 v = gx[i];
            int row = i >> 3, c4 = (i & 7) << 2;
            int r = row & 127, hi = row >> 7;
            float* base = xpf + ((r * 33 + c4) << 1) + hi;
            base[0] = v.x; base[2] = v.y; base[4] = v.z; base[6] = v.w;
        }
    }
    __syncthreads();

    const int ba = b0 + t;
    const int bb = b0 + 128 + t;

    float ldaccA, ldaccB;
    {
        float p[NP];
#pragma unroll
        for (int j = 0; j < NP; j++) p[j] = init_param[j];   // uniform broadcast
        float xa, xb, ld;
        unpack2(xp[t * 33], xa, xb);
        zout[(size_t)ba * DIMN] = spline_fwd(xa, p, &ld);
        ldaccA = ld;
        zout[(size_t)bb * DIMN] = spline_fwd(xb, p, &ld);
        ldaccB = ld;
    }

    for (int l = 0; l < LNUM; l++) {
        __syncthreads();
        // stage layer-l weights, duplicated into both f32x2 halves
        {
            for (int i = t; i < 31 * 32; i += 128) { float w = w1[l * 992 + i];  w1p[i] = pack2(w, w); }
            for (int i = t; i < 32 * 32; i += 128) { float w = w2[l * 1024 + i]; w2p[i] = pack2(w, w); }
            for (int i = t; i < 32 * 23; i += 128) {
                int r = i / 23, c = i - r * 23;
                float w = w3[l * 736 + i];
                w3p[r * 24 + c] = pack2(w, w);
            }
            if (t < 32) {
                float v1 = b1[l * 32 + t]; b1p[t] = pack2(v1, v1);
                float v2 = b2[l * 32 + t]; b2p[t] = pack2(v2, v2);
            }
            if (t < NP) { float v3 = b3[l * NP + t]; b3p[t] = pack2(v3, v3); }
        }
        __syncthreads();

        // ---- h1 = tanh(x[:, :l+1] @ w1 + b1), packed pair ----
        u64 h1[HID];
#pragma unroll
        for (int h = 0; h < HID; h++) h1[h] = b1p[h];
        for (int d = 0; d <= l; d++) {
            u64 xd = xp[t * 33 + d];
#pragma unroll
            for (int h = 0; h < HID; h++)
                h1[h] = ffma2(xd, w1p[d * 32 + h], h1[h]);
        }
#pragma unroll
        for (int h = 0; h < HID; h++) {
            float a, b; unpack2(h1[h], a, b);
            h1[h] = pack2(fast_tanh(a), fast_tanh(b));
        }

        // ---- h2 = tanh(h1 @ w2 + b2) ----
        u64 h2[HID];
#pragma unroll
        for (int h = 0; h < HID; h++) h2[h] = b2p[h];
#pragma unroll
        for (int d = 0; d < HID; d++) {
            u64 v = h1[d];
#pragma unroll
            for (int h = 0; h < HID; h++)
                h2[h] = ffma2(v, w2p[d * 32 + h], h2[h]);
        }
#pragma unroll
        for (int h = 0; h < HID; h++) {
            float a, b; unpack2(h2[h], a, b);
            h2[h] = pack2(fast_tanh(a), fast_tanh(b));
        }

        // ---- p = h2 @ w3 + b3 ----
        u64 pp[NP];
#pragma unroll
        for (int j = 0; j < NP; j++) pp[j] = b3p[j];
#pragma unroll
        for (int d = 0; d < HID; d++) {
            u64 v = h2[d];
#pragma unroll
            for (int j = 0; j < NP; j++)
                pp[j] = ffma2(v, w3p[d * 24 + j], pp[j]);
        }

        // ---- splines (scalar per element) ----
        float pa[NP], pb[NP];
#pragma unroll
        for (int j = 0; j < NP; j++) unpack2(pp[j], pa[j], pb[j]);

        float xa, xb, ld;
        unpack2(xp[t * 33 + l + 1], xa, xb);
        zout[(size_t)ba * DIMN + l + 1] = spline_fwd(xa, pa, &ld);
        ldaccA += ld;
        zout[(size_t)bb * DIMN + l + 1] = spline_fwd(xb, pb, &ld);
        ldaccB += ld;
    }

    if (write_ld) { ldout[ba] = ldaccA; ldout[bb] = ldaccB; }
}

extern "C" void kernel_launch(void* const* d_in, const int* in_sizes, int n_in,
                              void* d_out, int out_size) {
    const float* x          = (const float*)d_in[0];
    const float* init_param = (const float*)d_in[1];
    const float* w1 = (const float*)d_in[2];
    const float* b1 = (const float*)d_in[3];
    const float* w2 = (const float*)d_in[4];
    const float* b2 = (const float*)d_in[5];
    const float* w3 = (const float*)d_in[6];
    const float* b3 = (const float*)d_in[7];

    float* out = (float*)d_out;
    int write_ld = (out_size >= BATCH * DIMN + BATCH) ? 1 : 0;

    nsf_ar_kernel<<<BATCH / 256, 128>>>(x, init_param, w1, b1, w2, b2, w3, b3,
                                        out, out + (size_t)BATCH * DIMN, write_ld);
}